// round 15
// baseline (speedup 1.0000x reference)
#include <cuda_runtime.h>
#include <cuda_bf16.h>

// out[n,:] = x[n,:] * min(1, 1/||x[n,:]||) + noise[n,:]   (L2_NORM_CLIP = 1)
// N = 524288 rows, D = 128 fp32.
//
// PERSISTENT one-wave grid (SMs x max-resident-CTAs), one warp per ROW-PAIR
// per iteration. Each warp streams ~20+ pairs with a 1-deep software
// pipeline: next pair's 4 LDG.128/thread are issued before the current
// pair's two interleaved shfl reductions + 2 STG.128. Queues stay full for
// the whole kernel: no wave transitions, no cold pipeline restarts.
// Zero-reuse traffic -> .cs streaming hints on all loads/stores.

__global__ __launch_bounds__(256) void dp_clip_noise_kernel(
    const float4* __restrict__ x,
    const float4* __restrict__ noise,
    float4* __restrict__ out,
    int npairs)
{
    const int lane   = threadIdx.x & 31;
    const int warp   = (int)((blockIdx.x * blockDim.x + threadIdx.x) >> 5);
    const int nwarps = (int)((gridDim.x * blockDim.x) >> 5);

    int pair = warp;
    if (pair >= npairs) return;

    const long long stride = (long long)nwarps * 64;  // float4s per pair-step

    // Pair p covers float4 indices [p*64, p*64+64): row 2p at +lane,
    // row 2p+1 at +32+lane.
    long long idx = (long long)pair * 64 + lane;
    float4 xv0 = __ldcs(x + idx);
    float4 nv0 = __ldcs(noise + idx);
    float4 xv1 = __ldcs(x + idx + 32);
    float4 nv1 = __ldcs(noise + idx + 32);

    while (true) {
        // ---- prefetch next pair (issued before the reduction chains) ----
        const int  next = pair + nwarps;
        const bool more = next < npairs;
        float4 xp0, np0, xp1, np1;
        const long long nidx = idx + stride;
        if (more) {
            xp0 = __ldcs(x + nidx);
            np0 = __ldcs(noise + nidx);
            xp1 = __ldcs(x + nidx + 32);
            np1 = __ldcs(noise + nidx + 32);
        }

        // ---- two independent reductions, interleaved for ILP ----
        float s0 = xv0.x * xv0.x + xv0.y * xv0.y + xv0.z * xv0.z + xv0.w * xv0.w;
        float s1 = xv1.x * xv1.x + xv1.y * xv1.y + xv1.z * xv1.z + xv1.w * xv1.w;
        #pragma unroll
        for (int off = 16; off > 0; off >>= 1) {
            s0 += __shfl_xor_sync(0xFFFFFFFFu, s0, off);
            s1 += __shfl_xor_sync(0xFFFFFFFFu, s1, off);
        }

        // scale = 1/max(norm,1) = min(1, rsqrt(ssq)); ssq==0 -> inf -> 1.
        const float sc0 = fminf(1.0f, rsqrtf(s0));
        const float sc1 = fminf(1.0f, rsqrtf(s1));

        float4 o0, o1;
        o0.x = fmaf(xv0.x, sc0, nv0.x);
        o0.y = fmaf(xv0.y, sc0, nv0.y);
        o0.z = fmaf(xv0.z, sc0, nv0.z);
        o0.w = fmaf(xv0.w, sc0, nv0.w);
        o1.x = fmaf(xv1.x, sc1, nv1.x);
        o1.y = fmaf(xv1.y, sc1, nv1.y);
        o1.z = fmaf(xv1.z, sc1, nv1.z);
        o1.w = fmaf(xv1.w, sc1, nv1.w);
        __stcs(out + idx,      o0);
        __stcs(out + idx + 32, o1);

        if (!more) break;
        pair = next;
        idx  = nidx;
        xv0 = xp0; nv0 = np0;
        xv1 = xp1; nv1 = np1;
    }
}

extern "C" void kernel_launch(void* const* d_in, const int* in_sizes, int n_in,
                              void* d_out, int out_size)
{
    const float4* x     = (const float4*)d_in[0];
    const float4* noise = (const float4*)d_in[1];
    float4* out         = (float4*)d_out;

    const int D = 128;
    const int nrows  = in_sizes[0] / D;         // 524288
    const int npairs = nrows / 2;               // 262144

    // Persistent one-wave grid: exactly the number of CTAs that fit
    // simultaneously on the chip (host-side queries, capture-safe).
    const int threads = 256;
    static int blocks = 0;                      // computed once; deterministic
    if (blocks == 0) {
        int dev = 0, sms = 148, occ = 4;
        cudaGetDevice(&dev);
        cudaDeviceGetAttribute(&sms, cudaDevAttrMultiProcessorCount, dev);
        cudaOccupancyMaxActiveBlocksPerMultiprocessor(
            &occ, dp_clip_noise_kernel, threads, 0);
        if (occ < 1) occ = 1;
        blocks = sms * occ;
        // Never launch more CTAs than there are pairs.
        const int warps_needed = npairs;
        const int max_blocks = (warps_needed + (threads / 32) - 1) / (threads / 32);
        if (blocks > max_blocks) blocks = max_blocks;
        if (blocks < 1) blocks = 1;
    }

    dp_clip_noise_kernel<<<blocks, threads>>>(x, noise, out, npairs);
}

// round 16
// speedup vs baseline: 1.0741x; 1.0741x over previous
#include <cuda_runtime.h>
#include <cuda_bf16.h>

// out[n,:] = x[n,:] * min(1, 1/||x[n,:]||) + noise[n,:]   (L2_NORM_CLIP = 1)
// N = 524288 rows, D = 128 fp32.
//
// One warp per 4-ROW GROUP per iteration, 2 iterations per warp (8192 CTAs:
// multi-wave so the HW scheduler rebalances per-CTA spread — a persistent
// one-wave grid measurably regressed). Per iteration: 8 front-batched
// LDG.128 per thread (+8 prefetched for the next group = up to 16 in
// flight), then FOUR independent shfl reduction chains interleaved (ILP=4),
// then 4 STG.128. 32-bit element indexing (16.7M float4s < 2^31).
// Zero-reuse traffic -> .cs streaming hints on all loads/stores.

__global__ __launch_bounds__(256) void dp_clip_noise_kernel(
    const float4* __restrict__ x,
    const float4* __restrict__ noise,
    float4* __restrict__ out,
    int ngroups)   // ngroups = nrows / 4
{
    const int lane   = threadIdx.x & 31;
    const int warp   = (int)((blockIdx.x * blockDim.x + threadIdx.x) >> 5);
    const int nwarps = (int)((gridDim.x * blockDim.x) >> 5);

    int grp = warp;
    if (grp >= ngroups) return;

    const int stride = nwarps * 128;           // float4s per group-step

    // Group g covers float4 indices [g*128, g*128+128): rows 4g..4g+3 at
    // +lane, +32+lane, +64+lane, +96+lane.
    int idx = grp * 128 + lane;
    float4 xv0 = __ldcs(x + idx);
    float4 nv0 = __ldcs(noise + idx);
    float4 xv1 = __ldcs(x + idx + 32);
    float4 nv1 = __ldcs(noise + idx + 32);
    float4 xv2 = __ldcs(x + idx + 64);
    float4 nv2 = __ldcs(noise + idx + 64);
    float4 xv3 = __ldcs(x + idx + 96);
    float4 nv3 = __ldcs(noise + idx + 96);

    while (true) {
        // ---- prefetch next group (issued before the reduction chains) ----
        const int  next = grp + nwarps;
        const bool more = next < ngroups;
        float4 xp0, np0, xp1, np1, xp2, np2, xp3, np3;
        const int nidx = idx + stride;
        if (more) {
            xp0 = __ldcs(x + nidx);
            np0 = __ldcs(noise + nidx);
            xp1 = __ldcs(x + nidx + 32);
            np1 = __ldcs(noise + nidx + 32);
            xp2 = __ldcs(x + nidx + 64);
            np2 = __ldcs(noise + nidx + 64);
            xp3 = __ldcs(x + nidx + 96);
            np3 = __ldcs(noise + nidx + 96);
        }

        // ---- four independent reductions, interleaved for ILP ----
        float s0 = xv0.x * xv0.x + xv0.y * xv0.y + xv0.z * xv0.z + xv0.w * xv0.w;
        float s1 = xv1.x * xv1.x + xv1.y * xv1.y + xv1.z * xv1.z + xv1.w * xv1.w;
        float s2 = xv2.x * xv2.x + xv2.y * xv2.y + xv2.z * xv2.z + xv2.w * xv2.w;
        float s3 = xv3.x * xv3.x + xv3.y * xv3.y + xv3.z * xv3.z + xv3.w * xv3.w;
        #pragma unroll
        for (int off = 16; off > 0; off >>= 1) {
            s0 += __shfl_xor_sync(0xFFFFFFFFu, s0, off);
            s1 += __shfl_xor_sync(0xFFFFFFFFu, s1, off);
            s2 += __shfl_xor_sync(0xFFFFFFFFu, s2, off);
            s3 += __shfl_xor_sync(0xFFFFFFFFu, s3, off);
        }

        // scale = 1/max(norm,1) = min(1, rsqrt(ssq)); ssq==0 -> inf -> 1.
        const float sc0 = fminf(1.0f, rsqrtf(s0));
        const float sc1 = fminf(1.0f, rsqrtf(s1));
        const float sc2 = fminf(1.0f, rsqrtf(s2));
        const float sc3 = fminf(1.0f, rsqrtf(s3));

        float4 o;
        o.x = fmaf(xv0.x, sc0, nv0.x); o.y = fmaf(xv0.y, sc0, nv0.y);
        o.z = fmaf(xv0.z, sc0, nv0.z); o.w = fmaf(xv0.w, sc0, nv0.w);
        __stcs(out + idx, o);
        o.x = fmaf(xv1.x, sc1, nv1.x); o.y = fmaf(xv1.y, sc1, nv1.y);
        o.z = fmaf(xv1.z, sc1, nv1.z); o.w = fmaf(xv1.w, sc1, nv1.w);
        __stcs(out + idx + 32, o);
        o.x = fmaf(xv2.x, sc2, nv2.x); o.y = fmaf(xv2.y, sc2, nv2.y);
        o.z = fmaf(xv2.z, sc2, nv2.z); o.w = fmaf(xv2.w, sc2, nv2.w);
        __stcs(out + idx + 64, o);
        o.x = fmaf(xv3.x, sc3, nv3.x); o.y = fmaf(xv3.y, sc3, nv3.y);
        o.z = fmaf(xv3.z, sc3, nv3.z); o.w = fmaf(xv3.w, sc3, nv3.w);
        __stcs(out + idx + 96, o);

        if (!more) break;
        grp = next;
        idx = nidx;
        xv0 = xp0; nv0 = np0;
        xv1 = xp1; nv1 = np1;
        xv2 = xp2; nv2 = np2;
        xv3 = xp3; nv3 = np3;
    }
}

extern "C" void kernel_launch(void* const* d_in, const int* in_sizes, int n_in,
                              void* d_out, int out_size)
{
    const float4* x     = (const float4*)d_in[0];
    const float4* noise = (const float4*)d_in[1];
    float4* out         = (float4*)d_out;

    const int D = 128;
    const int nrows   = in_sizes[0] / D;        // 524288
    const int ngroups = nrows / 4;              // 131072

    // 8 warps per CTA, 2 groups (8 rows) per warp -> 8192 CTAs.
    const int threads = 256;
    const int groups_per_warp = 2;
    const int warps_per_block = threads / 32;
    int blocks = (ngroups + warps_per_block * groups_per_warp - 1)
               / (warps_per_block * groups_per_warp);
    if (blocks < 1) blocks = 1;

    dp_clip_noise_kernel<<<blocks, threads>>>(x, noise, out, ngroups);
}

// round 17
// speedup vs baseline: 1.0767x; 1.0025x over previous
#include <cuda_runtime.h>
#include <cuda_bf16.h>

// out[n,:] = x[n,:] * min(1, 1/||x[n,:]||) + noise[n,:]   (L2_NORM_CLIP = 1)
// N = 524288 rows, D = 128 fp32.
//
// CONVERGED CONFIG (R14 family): one warp per ROW-PAIR, 2 pairs per warp,
// 16384 CTAs (multi-wave; HW scheduler rebalances per-CTA spread). 1-deep
// software pipeline: next pair's 4 LDG.128/thread are issued before the
// current pair's two interleaved shfl reductions + 2 STG.128.
// Measured at ~6.95 TB/s = the B300 chip-level LTS cap (~6300 B/cyc,
// path-independent); kernel time sits at the 768MB/6.95TB/s ≈ 110us floor.
// Tail refinement: prefetch is UNCONDITIONAL with a clamped index (the last
// iteration harmlessly re-reads its own pair), removing predicated loads
// from the hot loop.

__global__ __launch_bounds__(256) void dp_clip_noise_kernel(
    const float4* __restrict__ x,
    const float4* __restrict__ noise,
    float4* __restrict__ out,
    int npairs)
{
    const int lane   = threadIdx.x & 31;
    const int warp   = (int)((blockIdx.x * blockDim.x + threadIdx.x) >> 5);
    const int nwarps = (int)((gridDim.x * blockDim.x) >> 5);

    int pair = warp;
    if (pair >= npairs) return;

    // Pair p covers float4 indices [p*64, p*64+64): row 2p at +lane,
    // row 2p+1 at +32+lane.  (Total float4s = 16.7M < 2^31: 32-bit indexing.)
    int idx = pair * 64 + lane;
    float4 xv0 = __ldcs(x + idx);
    float4 nv0 = __ldcs(noise + idx);
    float4 xv1 = __ldcs(x + idx + 32);
    float4 nv1 = __ldcs(noise + idx + 32);

    while (true) {
        // ---- unconditional clamped prefetch (before the reduction) ----
        const int  next = pair + nwarps;
        const bool more = next < npairs;
        const int  nidx = more ? (idx + nwarps * 64) : idx;  // clamp to self
        float4 xp0 = __ldcs(x + nidx);
        float4 np0 = __ldcs(noise + nidx);
        float4 xp1 = __ldcs(x + nidx + 32);
        float4 np1 = __ldcs(noise + nidx + 32);

        // ---- two independent reductions, interleaved for ILP ----
        float s0 = xv0.x * xv0.x + xv0.y * xv0.y + xv0.z * xv0.z + xv0.w * xv0.w;
        float s1 = xv1.x * xv1.x + xv1.y * xv1.y + xv1.z * xv1.z + xv1.w * xv1.w;
        #pragma unroll
        for (int off = 16; off > 0; off >>= 1) {
            s0 += __shfl_xor_sync(0xFFFFFFFFu, s0, off);
            s1 += __shfl_xor_sync(0xFFFFFFFFu, s1, off);
        }

        // scale = 1/max(norm,1) = min(1, rsqrt(ssq)); ssq==0 -> inf -> 1.
        const float sc0 = fminf(1.0f, rsqrtf(s0));
        const float sc1 = fminf(1.0f, rsqrtf(s1));

        float4 o0, o1;
        o0.x = fmaf(xv0.x, sc0, nv0.x);
        o0.y = fmaf(xv0.y, sc0, nv0.y);
        o0.z = fmaf(xv0.z, sc0, nv0.z);
        o0.w = fmaf(xv0.w, sc0, nv0.w);
        o1.x = fmaf(xv1.x, sc1, nv1.x);
        o1.y = fmaf(xv1.y, sc1, nv1.y);
        o1.z = fmaf(xv1.z, sc1, nv1.z);
        o1.w = fmaf(xv1.w, sc1, nv1.w);
        __stcs(out + idx,      o0);
        __stcs(out + idx + 32, o1);

        if (!more) break;
        pair = next;
        idx  = nidx;
        xv0 = xp0; nv0 = np0;
        xv1 = xp1; nv1 = np1;
    }
}

extern "C" void kernel_launch(void* const* d_in, const int* in_sizes, int n_in,
                              void* d_out, int out_size)
{
    const float4* x     = (const float4*)d_in[0];
    const float4* noise = (const float4*)d_in[1];
    float4* out         = (float4*)d_out;

    const int D = 128;
    const int nrows  = in_sizes[0] / D;         // 524288
    const int npairs = nrows / 2;               // 262144

    // 8 warps per CTA, 2 pairs (4 rows) per warp -> 16384 CTAs.
    const int threads = 256;
    const int pairs_per_warp = 2;
    const int warps_per_block = threads / 32;
    int blocks = (npairs + warps_per_block * pairs_per_warp - 1)
               / (warps_per_block * pairs_per_warp);
    if (blocks < 1) blocks = 1;

    dp_clip_noise_kernel<<<blocks, threads>>>(x, noise, out, npairs);
}